// round 10
// baseline (speedup 1.0000x reference)
#include <cuda_runtime.h>
#include <cstdint>

// SAG_4861902979729: X_out[i] = sum_{e in [rp[i], rp[i+1])} X[ci[e]]
// X [N=100000, D=100] f32. rp [N+1], ci [E] int32/int64 (runtime-detected).
//
// R10: attack the within-LDG replay rate. A 25-lane LDG.E.128 over a 400B row
// spans 4 lines -> 4 wavefronts at the within-LDG replay rate (~2.07 cyc/wf)
// = ~8.3 cyc/neighbor = the ~85us ncu floor seen in R4/R5/R8/R9. Cross-LDG
// wavefronts pipeline at ~1.0 cyc/wf, so the same 4 lines issued as TWO
// predicated LDGs (each with active lanes confined to one 2-line pair) cost
// ~4-5 cyc/neighbor. Row j starts at chunk offset o=(25j)&7 in its line;
// lane l is in group A iff o+l<16 else B (l<25). Both predicated loads write
// the same dest regs -> no extra register pressure. R4 scaffold (1 row/warp).

#define D_DIM 100
#define VEC_PER_ROW 25   // 100 floats / 4 per float4

__device__ __forceinline__ void acc_add(float4& a, const float4& v) {
    a.x += v.x; a.y += v.y; a.z += v.z; a.w += v.w;
}

// Split gather: two predicated LDG.E.128 with lane groups confined to
// disjoint line pairs. t = (25*j & 7) + lane; A: t<16, B: t>=16 && lane<25.
// Lanes 25..31 load nothing (dest regs stale garbage; never stored).
__device__ __forceinline__
float4 ldg_split(const float* __restrict__ p, int t, int lane)
{
    float4 v;
    asm("{\n\t"
        ".reg .pred pa, pb, pl;\n\t"
        "setp.lt.s32 pa, %5, 16;\n\t"
        "setp.lt.s32 pl, %6, 25;\n\t"
        "setp.ge.and.s32 pb, %5, 16, pl;\n\t"
        "@pa ld.global.nc.v4.f32 {%0,%1,%2,%3}, [%4];\n\t"
        "@pb ld.global.nc.v4.f32 {%0,%1,%2,%3}, [%4];\n\t"
        "}"
        : "=f"(v.x), "=f"(v.y), "=f"(v.z), "=f"(v.w)
        : "l"(p), "r"(t), "r"(lane));
    return v;
}

// deg==32 fast path: 8 groups x 4 neighbors, split gathers.
__device__ __forceinline__
float4 gather32_split(const float* __restrict__ X, int my_idx, int lane,
                      size_t lane_off)
{
    float4 acc = make_float4(0.f, 0.f, 0.f, 0.f);
    #pragma unroll
    for (int g = 0; g < 8; g++) {
        const int j0 = __shfl_sync(0xffffffffu, my_idx, g * 4 + 0);
        const int j1 = __shfl_sync(0xffffffffu, my_idx, g * 4 + 1);
        const int j2 = __shfl_sync(0xffffffffu, my_idx, g * 4 + 2);
        const int j3 = __shfl_sync(0xffffffffu, my_idx, g * 4 + 3);

        const float4 v0 = ldg_split(X + (size_t)j0 * D_DIM + lane_off,
                                    ((j0 * 25) & 7) + lane, lane);
        const float4 v1 = ldg_split(X + (size_t)j1 * D_DIM + lane_off,
                                    ((j1 * 25) & 7) + lane, lane);
        const float4 v2 = ldg_split(X + (size_t)j2 * D_DIM + lane_off,
                                    ((j2 * 25) & 7) + lane, lane);
        const float4 v3 = ldg_split(X + (size_t)j3 * D_DIM + lane_off,
                                    ((j3 * 25) & 7) + lane, lane);

        // Inactive lanes (25..31) accumulate stale garbage; never stored.
        acc.x += (v0.x + v1.x) + (v2.x + v3.x);
        acc.y += (v0.y + v1.y) + (v2.y + v3.y);
        acc.z += (v0.z + v1.z) + (v2.z + v3.z);
        acc.w += (v0.w + v1.w) + (v2.w + v3.w);
    }
    return acc;
}

// Generic path (any degree / any index type): plain spanning loads.
template <typename IT>
__device__ __forceinline__
void sag_row_generic(const float* __restrict__ X,
                     const IT* __restrict__ rp,
                     const IT* __restrict__ ci,
                     float* __restrict__ out,
                     int row, int lane, bool active, size_t lane_off)
{
    const long long start = (long long)rp[row];
    const int deg = (int)((long long)rp[row + 1] - start);

    float4 acc = make_float4(0.f, 0.f, 0.f, 0.f);
    for (int k0 = 0; k0 < deg; k0 += 32) {
        const int cnt = min(32, deg - k0);
        int my_idx = 0;
        if (lane < cnt) my_idx = (int)__ldcs(ci + start + k0 + lane);
        for (int k = 0; k < cnt; k++) {
            const int j = __shfl_sync(0xffffffffu, my_idx, k);
            if (active) {
                const float4 v = *(const float4*)(X + (size_t)j * D_DIM + lane_off);
                acc_add(acc, v);
            }
        }
    }
    if (active)
        __stcs((float4*)(out + (size_t)row * D_DIM + lane_off), acc);
}

__global__ __launch_bounds__(256)
void sag_warp_row_kernel(const float* __restrict__ X,
                         const void* __restrict__ rp_raw,
                         const void* __restrict__ ci_raw,
                         float* __restrict__ out,
                         int n)
{
    const int lane = threadIdx.x & 31;
    const int row  = (blockIdx.x * blockDim.x + threadIdx.x) >> 5;
    if (row >= n) return;

    const bool active = (lane < VEC_PER_ROW);
    const size_t lane_off = (size_t)lane * 4;

    // Runtime index-width probe: two ALIGNED scalar 4B loads (uniform result).
    // int32 rp: words [0,32,64,...] -> w1 != 0
    // int64 rp: words [0,0,32,0,..] -> w1 == 0 && w2 != 0
    const int* rp_words = (const int*)rp_raw;
    const int w1 = __ldg(rp_words + 1);
    const int w2 = __ldg(rp_words + 2);
    const bool is64 = (w1 == 0) && (w2 != 0);

    if (!is64) {
        const int* rp = (const int*)rp_raw;
        const int* ci = (const int*)ci_raw;
        const int start = __ldg(rp + row);
        const int deg   = __ldg(rp + row + 1) - start;

        if (deg == 32) {
            const int my_idx = (int)__ldcs(ci + start + lane);
            const float4 acc = gather32_split(X, my_idx, lane, lane_off);
            if (active)
                __stcs((float4*)(out + (size_t)row * D_DIM + lane_off), acc);
        } else {
            sag_row_generic<int>(X, rp, ci, out, row, lane, active, lane_off);
        }
    } else {
        const long long* rp = (const long long*)rp_raw;
        const long long* ci = (const long long*)ci_raw;
        sag_row_generic<long long>(X, rp, ci, out, row, lane, active, lane_off);
    }
}

extern "C" void kernel_launch(void* const* d_in, const int* in_sizes, int n_in,
                              void* d_out, int out_size)
{
    const float* X   = (const float*)d_in[0];
    const void*  rp  = d_in[1];
    const void*  ci  = d_in[2];
    float*       out = (float*)d_out;

    const int n = in_sizes[1] - 1;           // row_pointers has N+1 entries

    const int threads = 256;                  // 8 warps/block, 1 row per warp
    const int warps_per_block = threads / 32;
    const int blocks = (n + warps_per_block - 1) / warps_per_block;

    sag_warp_row_kernel<<<blocks, threads>>>(X, rp, ci, out, n);
}

// round 11
// speedup vs baseline: 2.3084x; 2.3084x over previous
#include <cuda_runtime.h>
#include <cstdint>

// SAG_4861902979729: X_out[i] = sum_{e in [rp[i], rp[i+1])} X[ci[e]]
// X [N=100000, D=100] f32. rp [N+1], ci [E] int32/int64 (runtime-detected).
//
// R11: retry of the split-gather theory WITHOUT inline asm (R10's asm blew
// registers to 128 and occupancy to 23%). A 25-lane LDG.E.128 over a 400B row
// spans 4 lines -> 4 L1tex wavefronts at the within-LDG replay rate (~2.07
// cyc/wf) ~= 8.3 cyc/neighbor = the ~85us floor of R4/R5/R8/R9. Splitting
// each gather into TWO predicated LDGs whose active lanes cover disjoint
// 2-line pairs converts them to cross-LDG pricing (~1.0 cyc/wf).
// Codegen trick: group A uses __ldg (LDG.E.CONSTANT), group B a plain deref
// (LDG.E) -> distinct opcodes, cannot be re-merged by the compiler; both are
// L1-cached; ptxas predicates the single-load arms.
// Geometry: X base 256B-aligned; row j starts at line-chunk offset
// (25j mod 8) == j&7 (25 = 1 mod 8). Lane l's chunk t=(j&7)+l; t<16 -> lines
// 0-1 (group A), else lines 2-3 (group B). Lanes 25..31 load nothing.

#define D_DIM 100
#define VEC_PER_ROW 25   // 100 floats / 4 per float4

__device__ __forceinline__ void acc_add(float4& a, const float4& v) {
    a.x += v.x; a.y += v.y; a.z += v.z; a.w += v.w;
}

// Split gather of one neighbor row chunk for this lane.
__device__ __forceinline__
float4 gather_one(const float* __restrict__ X, int j, int lane, size_t lane_off)
{
    const float4* p = (const float4*)(X + (size_t)j * D_DIM + lane_off);
    const int t = (j & 7) + lane;
    float4 v = make_float4(0.f, 0.f, 0.f, 0.f);
    if (lane < VEC_PER_ROW) {
        if (t < 16) v = __ldg(p);        // LDG.E.CONSTANT — lines 0-1
        else        v = *p;              // LDG.E          — lines 2-3
    }
    return v;
}

// deg==32 fast path: 8 groups x 4 neighbors (proven R4 liveness shape).
__device__ __forceinline__
float4 gather32_split(const float* __restrict__ X, int my_idx, int lane,
                      size_t lane_off)
{
    float4 acc = make_float4(0.f, 0.f, 0.f, 0.f);
    #pragma unroll
    for (int g = 0; g < 8; g++) {
        const int j0 = __shfl_sync(0xffffffffu, my_idx, g * 4 + 0);
        const int j1 = __shfl_sync(0xffffffffu, my_idx, g * 4 + 1);
        const int j2 = __shfl_sync(0xffffffffu, my_idx, g * 4 + 2);
        const int j3 = __shfl_sync(0xffffffffu, my_idx, g * 4 + 3);

        const float4 v0 = gather_one(X, j0, lane, lane_off);
        const float4 v1 = gather_one(X, j1, lane, lane_off);
        const float4 v2 = gather_one(X, j2, lane, lane_off);
        const float4 v3 = gather_one(X, j3, lane, lane_off);

        acc.x += (v0.x + v1.x) + (v2.x + v3.x);
        acc.y += (v0.y + v1.y) + (v2.y + v3.y);
        acc.z += (v0.z + v1.z) + (v2.z + v3.z);
        acc.w += (v0.w + v1.w) + (v2.w + v3.w);
    }
    return acc;
}

// Generic path (any degree / any index type): plain spanning loads.
template <typename IT>
__device__ __forceinline__
void sag_row_generic(const float* __restrict__ X,
                     const IT* __restrict__ rp,
                     const IT* __restrict__ ci,
                     float* __restrict__ out,
                     int row, int lane, bool active, size_t lane_off)
{
    const long long start = (long long)rp[row];
    const int deg = (int)((long long)rp[row + 1] - start);

    float4 acc = make_float4(0.f, 0.f, 0.f, 0.f);
    for (int k0 = 0; k0 < deg; k0 += 32) {
        const int cnt = min(32, deg - k0);
        int my_idx = 0;
        if (lane < cnt) my_idx = (int)__ldcs(ci + start + k0 + lane);
        for (int k = 0; k < cnt; k++) {
            const int j = __shfl_sync(0xffffffffu, my_idx, k);
            if (active) {
                const float4 v = *(const float4*)(X + (size_t)j * D_DIM + lane_off);
                acc_add(acc, v);
            }
        }
    }
    if (active)
        __stcs((float4*)(out + (size_t)row * D_DIM + lane_off), acc);
}

__global__ __launch_bounds__(256)
void sag_warp_row_kernel(const float* __restrict__ X,
                         const void* __restrict__ rp_raw,
                         const void* __restrict__ ci_raw,
                         float* __restrict__ out,
                         int n)
{
    const int lane = threadIdx.x & 31;
    const int row  = (blockIdx.x * blockDim.x + threadIdx.x) >> 5;
    if (row >= n) return;

    const bool active = (lane < VEC_PER_ROW);
    const size_t lane_off = (size_t)lane * 4;

    // Runtime index-width probe: two ALIGNED scalar 4B loads (uniform result).
    // int32 rp: words [0,32,64,...] -> w1 != 0
    // int64 rp: words [0,0,32,0,..] -> w1 == 0 && w2 != 0
    const int* rp_words = (const int*)rp_raw;
    const int w1 = __ldg(rp_words + 1);
    const int w2 = __ldg(rp_words + 2);
    const bool is64 = (w1 == 0) && (w2 != 0);

    if (!is64) {
        const int* rp = (const int*)rp_raw;
        const int* ci = (const int*)ci_raw;
        const int start = __ldg(rp + row);
        const int deg   = __ldg(rp + row + 1) - start;

        if (deg == 32) {
            const int my_idx = (int)__ldcs(ci + start + lane);
            const float4 acc = gather32_split(X, my_idx, lane, lane_off);
            if (active)
                __stcs((float4*)(out + (size_t)row * D_DIM + lane_off), acc);
        } else {
            sag_row_generic<int>(X, rp, ci, out, row, lane, active, lane_off);
        }
    } else {
        const long long* rp = (const long long*)rp_raw;
        const long long* ci = (const long long*)ci_raw;
        sag_row_generic<long long>(X, rp, ci, out, row, lane, active, lane_off);
    }
}

extern "C" void kernel_launch(void* const* d_in, const int* in_sizes, int n_in,
                              void* d_out, int out_size)
{
    const float* X   = (const float*)d_in[0];
    const void*  rp  = d_in[1];
    const void*  ci  = d_in[2];
    float*       out = (float*)d_out;

    const int n = in_sizes[1] - 1;           // row_pointers has N+1 entries

    const int threads = 256;                  // 8 warps/block, 1 row per warp
    const int warps_per_block = threads / 32;
    const int blocks = (n + warps_per_block - 1) / warps_per_block;

    sag_warp_row_kernel<<<blocks, threads>>>(X, rp, ci, out, n);
}